// round 13
// baseline (speedup 1.0000x reference)
#include <cuda_runtime.h>
#include <cuda_fp16.h>
#include <math.h>
#include <stdint.h>

// Problem constants
#define B_ 8192
#define F_ 1024
#define U_ 512
#define O_ 3
#define A_ 6
#define H_ 4
#define HD_ 128

typedef __half h16;
#define BU_ ((size_t)B_ * U_)
#define UF_ ((size_t)U_ * F_)

// ===========================================================================
// Scratch (device globals)
// ===========================================================================
__device__ __align__(128) h16 g_feat[(size_t)B_ * F_];
__device__ __align__(128) h16 g_cat[(size_t)B_ * 2 * U_];     // [agent_latent | attn]
__device__ __align__(128) h16 g_opp[(size_t)O_ * B_ * U_];
__device__ __align__(128) h16 g_q[(size_t)B_ * U_];
__device__ __align__(128) h16 g_kv[(size_t)O_ * B_ * 2 * U_]; // [O][B][k|v]
__device__ __align__(128) h16 g_ah[(size_t)B_ * U_];
__device__ __align__(128) h16 g_oh[(size_t)O_ * B_ * U_];
__device__ __align__(128) float g_partial[(size_t)B_ * U_];   // agent_head partial (fp32)
// weights (fp16)
__device__ __align__(128) h16 g_Wbig[(size_t)4 * U_ * F_];    // [W_al | W_ol(3)]
__device__ __align__(128) h16 g_Win[(size_t)3 * U_ * U_];
__device__ __align__(128) h16 g_WoutT[(size_t)U_ * U_];       // W_out transposed
__device__ __align__(128) h16 g_Wah[(size_t)U_ * 2 * U_];     // full W_ah (comb A)
__device__ __align__(128) h16 g_Wah2[(size_t)U_ * 2 * U_];    // [W_ahL | W_comb]
__device__ __align__(128) h16 g_Woh[(size_t)O_ * U_ * U_];
__device__ __align__(128) float g_bcomb[U_];
__device__ __align__(128) float g_zero[U_];                   // stays zero

// ===========================================================================
// PTX helpers
// ===========================================================================
__device__ __forceinline__ uint32_t smem_u32(const void* p) {
    uint32_t a;
    asm("{ .reg .u64 t; cvta.to.shared.u64 t, %1; cvt.u32.u64 %0, t; }"
        : "=r"(a) : "l"(p));
    return a;
}
__device__ __forceinline__ void cp16(uint32_t s, const void* g) {
    asm volatile("cp.async.cg.shared.global [%0], [%1], 16;" :: "r"(s), "l"(g));
}
#define CP_COMMIT() asm volatile("cp.async.commit_group;" ::: "memory")
#define CP_WAIT0()  asm volatile("cp.async.wait_group 0;" ::: "memory")
#define CP_WAIT1()  asm volatile("cp.async.wait_group 1;" ::: "memory")

__device__ __forceinline__ void ldsm4(uint32_t* r, uint32_t addr) {
    asm volatile("ldmatrix.sync.aligned.m8n8.x4.shared.b16 {%0,%1,%2,%3}, [%4];"
                 : "=r"(r[0]), "=r"(r[1]), "=r"(r[2]), "=r"(r[3]) : "r"(addr));
}
__device__ __forceinline__ void mma_f16(float* c, const uint32_t* a, const uint32_t* b) {
    asm volatile("mma.sync.aligned.m16n8k16.row.col.f32.f16.f16.f32 "
                 "{%0,%1,%2,%3}, {%4,%5,%6,%7}, {%8,%9}, {%0,%1,%2,%3};"
                 : "+f"(c[0]), "+f"(c[1]), "+f"(c[2]), "+f"(c[3])
                 : "r"(a[0]), "r"(a[1]), "r"(a[2]), "r"(a[3]),
                   "r"(b[0]), "r"(b[1]));
}
__device__ __forceinline__ void unpack8(uint4 u, float* out) {
    const __half2* h = (const __half2*)&u;
#pragma unroll
    for (int j = 0; j < 4; j++) {
        float2 f = __half22float2(h[j]);
        out[2 * j] = f.x; out[2 * j + 1] = f.y;
    }
}
__device__ __forceinline__ float4 load_h4(const h16* p) {
    uint2 u = *(const uint2*)p;
    const __half2* h = (const __half2*)&u;
    float2 a = __half22float2(h[0]), b = __half22float2(h[1]);
    return make_float4(a.x, a.y, b.x, b.y);
}

// ===========================================================================
// One-shot convert + W_out transpose + W_ah-left copy
// ===========================================================================
#define CN0 ((int)((size_t)B_ * F_ / 4))
#define CN1 ((int)(UF_ / 4))
#define CN2 ((int)(3 * UF_ / 4))
#define CN3 ((int)(3 * (size_t)U_ * U_ / 4))
#define CN4 ((int)((size_t)U_ * U_ / 4))
#define CN5 ((int)(2 * (size_t)U_ * U_ / 4))
#define CN6 ((int)((size_t)U_ * U_ / 4))
#define CN7 ((int)(3 * (size_t)U_ * U_ / 4))
#define CTOT (CN0 + CN1 + CN2 + CN3 + CN4 + CN5 + CN6 + CN7)

__global__ void convert_all(const float* __restrict__ f,
                            const float* __restrict__ wal,
                            const float* __restrict__ wol,
                            const float* __restrict__ win,
                            const float* __restrict__ wout,
                            const float* __restrict__ wah,
                            const float* __restrict__ woh)
{
    int i = blockIdx.x * blockDim.x + threadIdx.x;
    if (i >= CTOT) return;
    const float* src; h16* dst; int off;
    if (i < CN0)                 { src = f;    dst = g_feat;       off = i; }
    else if ((i -= CN0) < CN1)   { src = wal;  dst = g_Wbig;       off = i; }
    else if ((i -= CN1) < CN2)   { src = wol;  dst = g_Wbig + UF_; off = i; }
    else if ((i -= CN2) < CN3)   { src = win;  dst = g_Win;        off = i; }
    else if ((i -= CN3) < CN4) {
        int n = i >> 7, k4 = i & 127;
        float4 x = ((const float4*)wout)[i];
        const float xs[4] = {x.x, x.y, x.z, x.w};
#pragma unroll
        for (int j = 0; j < 4; j++)
            g_WoutT[(size_t)(k4 * 4 + j) * U_ + n] = __float2half_rn(xs[j]);
        return;
    }
    else if ((i -= CN4) < CN5)   { src = wah;  dst = g_Wah;        off = i; }
    else if ((i -= CN5) < CN6) {
        int m = i >> 7, c4 = i & 127;
        int idx = m * 256 + c4;
        float4 x = ((const float4*)wah)[idx];
        h16 h[4] = {__float2half_rn(x.x), __float2half_rn(x.y),
                    __float2half_rn(x.z), __float2half_rn(x.w)};
        ((uint2*)g_Wah2)[idx] = *(uint2*)h;
        return;
    }
    else                         { src = woh;  dst = g_Woh;        off = i - CN6; }
    float4 x = ((const float4*)src)[off];
    h16 h[4] = {__float2half_rn(x.x), __float2half_rn(x.y),
                __float2half_rn(x.z), __float2half_rn(x.w)};
    ((uint2*)dst)[off] = *(uint2*)h;
}

// b_comb[m] = b_ah[m] + W_ahR[m,:] . b_out — warp per output
__global__ void bcomb_kernel(const float* __restrict__ wah,
                             const float* __restrict__ b_ah,
                             const float* __restrict__ b_out)
{
    const int w = (blockIdx.x * blockDim.x + threadIdx.x) >> 5;
    const int lane = threadIdx.x & 31;
    if (w >= U_) return;
    const float* row = wah + (size_t)w * 2 * U_ + U_;
    float s = 0.f;
#pragma unroll
    for (int j = 0; j < 16; j++) {
        const int n = lane + 32 * j;
        s += row[n] * b_out[n];
    }
#pragma unroll
    for (int off = 16; off > 0; off >>= 1) s += __shfl_xor_sync(~0u, s, off);
    if (lane == 0) g_bcomb[w] = s + b_ah[w];
}

// ===========================================================================
// GEMM core. mode 0: h16 out (elu flag). mode 1: fp32 partial out (no act).
// mode 2: read fp32 partial + add + elu + h16 out.
// ===========================================================================
#define MT 128
#define NT 128
#define KB 64
#define RSTRIDE 144
#define COMP_BYTES (128 * RSTRIDE)
#define OFF_A 0
#define OFF_W COMP_BYTES
#define STG_BYTES (2 * COMP_BYTES)
#define NSTAGE 3
#define GEMM_SMEM (1024 + NSTAGE * STG_BYTES)   // 111616

__device__ __forceinline__ void load_stage_async(
    uint32_t st, int tid,
    const h16* __restrict__ A, int lda, int mtile,
    const h16* __restrict__ W, int ldw, int ntile, int k0)
{
#pragma unroll
    for (int i = 0; i < 4; i++) {
        int idx = tid + i * 256;
        int r = idx >> 3, c = idx & 7;
        uint32_t so = (uint32_t)(r * RSTRIDE + c * 16);
        cp16(st + OFF_A + so, A + (size_t)(mtile + r) * lda + k0 + c * 8);
    }
#pragma unroll
    for (int i = 0; i < 4; i++) {
        int idx = tid + i * 256;
        int r = idx >> 3, c = idx & 7;
        uint32_t so = (uint32_t)(r * RSTRIDE + c * 16);
        cp16(st + OFF_W + so, W + (size_t)(ntile + r) * ldw + k0 + c * 8);
    }
    CP_COMMIT();
}

__device__ __forceinline__ void gemm_core(
    const h16* __restrict__ A, int lda,
    const h16* __restrict__ W, int ldw,
    const float* __restrict__ bias, float scale,
    h16* __restrict__ C, float* __restrict__ Pf, int ldc,
    int K, bool elu, int mode, char* smem)
{
    float* bias_s = (float*)smem;
    const uint32_t st0 = smem_u32(smem + 1024);

    const int tid = threadIdx.x, lane = tid & 31, wid = tid >> 5;
    const int wm = wid & 3, wn = wid >> 2;
    const int mtile = blockIdx.y * MT;
    const int ntile = blockIdx.x * NT;

    if (tid < NT) bias_s[tid] = bias[ntile + tid];

    float acc[2][8][4];
#pragma unroll
    for (int i = 0; i < 2; i++)
#pragma unroll
        for (int j = 0; j < 8; j++)
#pragma unroll
            for (int t = 0; t < 4; t++) acc[i][j][t] = 0.f;

    const int nc = K / KB;

    load_stage_async(st0, tid, A, lda, mtile, W, ldw, ntile, 0);
    load_stage_async(st0 + STG_BYTES, tid, A, lda, mtile, W, ldw, ntile, KB);

    const uint32_t a_row = (uint32_t)(lane & 15);
    const uint32_t a_koff = (uint32_t)((lane >> 4) * 16);
    const uint32_t b_row = (uint32_t)(((lane >> 4) * 8) + (lane & 7));
    const uint32_t b_koff = (uint32_t)(((lane >> 3) & 1) * 16);

    int sidx = 0;
    for (int c = 0; c < nc; ++c) {
        if (c + 1 < nc) CP_WAIT1(); else CP_WAIT0();
        __syncthreads();
        if (c + 2 < nc) {
            int nidx = sidx + 2; if (nidx >= NSTAGE) nidx -= NSTAGE;
            load_stage_async(st0 + nidx * STG_BYTES, tid,
                             A, lda, mtile, W, ldw, ntile, (c + 2) * KB);
        }
        const uint32_t cur = st0 + sidx * STG_BYTES;
#pragma unroll
        for (int kc = 0; kc < 4; kc++) {
            uint32_t af[2][4], wf[4][4];
#pragma unroll
            for (int mt = 0; mt < 2; mt++) {
                uint32_t row = wm * 32 + mt * 16 + a_row;
                ldsm4(af[mt], cur + OFF_A + row * RSTRIDE + kc * 32 + a_koff);
            }
#pragma unroll
            for (int q = 0; q < 4; q++) {
                uint32_t row = wn * 64 + q * 16 + b_row;
                ldsm4(wf[q], cur + OFF_W + row * RSTRIDE + kc * 32 + b_koff);
            }
#pragma unroll
            for (int mt = 0; mt < 2; mt++)
#pragma unroll
                for (int q = 0; q < 4; q++)
#pragma unroll
                    for (int s = 0; s < 2; s++)
                        mma_f16(acc[mt][2 * q + s], af[mt], &wf[q][2 * s]);
        }
        if (++sidx >= NSTAGE) sidx = 0;
    }

    const int g = lane >> 2, tg = lane & 3;
#pragma unroll
    for (int mt = 0; mt < 2; mt++) {
        const int m0 = mtile + wm * 32 + mt * 16 + g;
#pragma unroll
        for (int n8 = 0; n8 < 8; n8++) {
            const int nl = wn * 64 + n8 * 8 + tg * 2;
            const int n = ntile + nl;
            const float b0 = bias_s[nl], b1 = bias_s[nl + 1];
            float x0 = (acc[mt][n8][0] + b0) * scale;
            float x1 = (acc[mt][n8][1] + b1) * scale;
            float y0 = (acc[mt][n8][2] + b0) * scale;
            float y1 = (acc[mt][n8][3] + b1) * scale;
            if (mode == 1) {
                *(float2*)(Pf + (size_t)m0 * ldc + n) = make_float2(x0, x1);
                *(float2*)(Pf + (size_t)(m0 + 8) * ldc + n) = make_float2(y0, y1);
                continue;
            }
            if (mode == 2) {
                float2 p0 = *(const float2*)(Pf + (size_t)m0 * ldc + n);
                float2 p1 = *(const float2*)(Pf + (size_t)(m0 + 8) * ldc + n);
                x0 += p0.x; x1 += p0.y; y0 += p1.x; y1 += p1.y;
            }
            if (elu) {
                x0 = x0 > 0.f ? x0 : expm1f(x0);
                x1 = x1 > 0.f ? x1 : expm1f(x1);
                y0 = y0 > 0.f ? y0 : expm1f(y0);
                y1 = y1 > 0.f ? y1 : expm1f(y1);
            }
            union { h16 h[2]; uint32_t u; } p;
            p.h[0] = __float2half_rn(x0); p.h[1] = __float2half_rn(x1);
            *(uint32_t*)(C + (size_t)m0 * ldc + n) = p.u;
            p.h[0] = __float2half_rn(y0); p.h[1] = __float2half_rn(y1);
            *(uint32_t*)(C + (size_t)(m0 + 8) * ldc + n) = p.u;
        }
    }
}

// ---- mode wrappers ----
// K1: z=0 agent_latent; z=1..3 opp_lat; z=4 (y<4) W_comb.  grid (4, 64, 5)
__global__ void __launch_bounds__(256, 2)
gemm_k1(const float* __restrict__ b_al, const float* __restrict__ b_ol)
{
    extern __shared__ __align__(128) char smem[];
    const int z = blockIdx.z;
    if (z == 0)
        gemm_core(g_feat, F_, g_Wbig, F_, b_al, 1.f,
                  g_cat, nullptr, 2 * U_, F_, true, 0, smem);
    else if (z < 4)
        gemm_core(g_feat, F_, g_Wbig + (size_t)z * UF_, F_,
                  b_ol + (size_t)(z - 1) * U_, 1.f,
                  g_opp + (size_t)(z - 1) * BU_, nullptr, U_, F_, true, 0, smem);
    else {
        if (blockIdx.y >= 4) return;
        gemm_core(g_Wah + U_, 2 * U_, g_WoutT, U_, g_zero, 1.f,
                  g_Wah2 + U_, nullptr, 2 * U_, U_, false, 0, smem);
    }
}

// MID: zz=0 q; zz=1..6 kv halves; zz=7..9 opp_heads; zz=10 agent_head partial.
// grid (4, 64, 11), all K=512.
__global__ void __launch_bounds__(256, 2)
gemm_mid(const float* __restrict__ b_in, float qscale,
         const float* __restrict__ b_oh)
{
    extern __shared__ __align__(128) char smem[];
    const int zz = blockIdx.z;
    if (zz == 0) {
        gemm_core(g_cat, 2 * U_, g_Win, U_, b_in, qscale,
                  g_q, nullptr, U_, U_, false, 0, smem);
    } else if (zz <= 6) {
        const int o = (zz - 1) >> 1, half = (zz - 1) & 1;
        gemm_core(g_opp + (size_t)o * BU_, U_,
                  g_Win + (size_t)U_ * U_ + (size_t)half * 512 * U_, U_,
                  b_in + U_ + half * 512, 1.f,
                  g_kv + (size_t)o * B_ * 2 * U_ + half * 512, nullptr, 2 * U_,
                  U_, false, 0, smem);
    } else if (zz <= 9) {
        const int o = zz - 7;
        gemm_core(g_opp + (size_t)o * BU_, U_,
                  g_Woh + (size_t)o * U_ * U_, U_,
                  b_oh + (size_t)o * U_, 1.f,
                  g_oh + (size_t)o * BU_, nullptr, U_, U_, true, 0, smem);
    } else {
        // agent_head partial: cat_L @ W_ahL^T + b_comb -> fp32 partial
        gemm_core(g_cat, 2 * U_, g_Wah2, 2 * U_, g_bcomb, 1.f,
                  nullptr, g_partial, U_, U_, false, 1, smem);
    }
}

// FIN: agent_head finish: attn @ W_comb^T + partial, elu -> g_ah. grid (4,64,1)
__global__ void __launch_bounds__(256, 2)
gemm_fin()
{
    extern __shared__ __align__(128) char smem[];
    gemm_core(g_cat + U_, 2 * U_, g_Wah2 + U_, 2 * U_, g_zero, 1.f,
              g_ah, g_partial, U_, U_, true, 2, smem);
}

// ===========================================================================
// Attention — 2 rows per 256-thread CTA; writes attn into cat[:, U:]
// ===========================================================================
__global__ void attention_kernel(float* __restrict__ infl)
{
    const int tid = threadIdx.x;
    const int sub = tid >> 7;
    const int ltid = tid & 127;
    const int b = blockIdx.x * 2 + sub;
    const int h = ltid >> 5;
    const int lane = tid & 31;
    __shared__ float sw[2][H_][O_];

    const size_t qbase = (size_t)b * U_ + (size_t)h * HD_;
    const float4 qv = load_h4(g_q + qbase + lane * 4);

    float s[O_];
#pragma unroll
    for (int o = 0; o < O_; o++) {
        const size_t kb = ((size_t)o * B_ + b) * (2 * U_) + (size_t)h * HD_;
        const float4 kvv = load_h4(g_kv + kb + lane * 4);
        float d = qv.x * kvv.x + qv.y * kvv.y + qv.z * kvv.z + qv.w * kvv.w;
#pragma unroll
        for (int off = 16; off > 0; off >>= 1)
            d += __shfl_xor_sync(0xffffffffu, d, off);
        s[o] = d;
    }
    const float m = fmaxf(s[0], fmaxf(s[1], s[2]));
    const float e0 = expf(s[0] - m), e1 = expf(s[1] - m), e2 = expf(s[2] - m);
    const float inv = 1.f / (e0 + e1 + e2);
    const float w[O_] = {e0 * inv, e1 * inv, e2 * inv};

    float4 a = make_float4(0.f, 0.f, 0.f, 0.f);
#pragma unroll
    for (int o = 0; o < O_; o++) {
        const size_t vb = ((size_t)o * B_ + b) * (2 * U_) + U_ + (size_t)h * HD_;
        const float4 vv = load_h4(g_kv + vb + lane * 4);
        a.x = fmaf(w[o], vv.x, a.x);
        a.y = fmaf(w[o], vv.y, a.y);
        a.z = fmaf(w[o], vv.z, a.z);
        a.w = fmaf(w[o], vv.w, a.w);
    }
    {
        union { h16 h[4]; uint2 u; } uh;
        uh.h[0] = __float2half_rn(a.x); uh.h[1] = __float2half_rn(a.y);
        uh.h[2] = __float2half_rn(a.z); uh.h[3] = __float2half_rn(a.w);
        *(uint2*)(g_cat + (size_t)b * 2 * U_ + U_ + (size_t)h * HD_ + lane * 4) = uh.u;
    }

    if (lane == 0) {
        sw[sub][h][0] = w[0]; sw[sub][h][1] = w[1]; sw[sub][h][2] = w[2];
    }
    __syncthreads();
    if (ltid < O_)
        infl[(size_t)b * O_ + ltid] =
            0.25f * (sw[sub][0][ltid] + sw[sub][1][ltid] +
                     sw[sub][2][ltid] + sw[sub][3][ltid]);
}

// ===========================================================================
// Fused skinny heads — grid (B/8, 4): y=0 agent (g_ah), y>0 opp o=y-1 (g_oh)
// ===========================================================================
__global__ void skinny_all(const float* __restrict__ W_ap, const float* __restrict__ b_ap,
                           const float* __restrict__ W_av, const float* __restrict__ b_av,
                           const float* __restrict__ W_op, const float* __restrict__ b_op,
                           const float* __restrict__ W_ov, const float* __restrict__ b_ov,
                           float* __restrict__ agent_pol, float* __restrict__ agent_val,
                           float* __restrict__ opp_pol, float* __restrict__ opp_val)
{
    const int wid = threadIdx.x >> 5, lane = threadIdx.x & 31;
    const int b = blockIdx.x * 8 + wid;
    const int y = blockIdx.y;

    const h16* act; const float *Wp, *bp, *Wv, *bv;
    if (y == 0) {
        act = g_ah + (size_t)b * U_;
        Wp = W_ap; bp = b_ap; Wv = W_av; bv = b_av;
    } else {
        const int o = y - 1;
        act = g_oh + ((size_t)o * B_ + b) * U_;
        Wp = W_op + (size_t)o * A_ * U_; bp = b_op + o * A_;
        Wv = W_ov + (size_t)o * U_;      bv = b_ov + o;
    }

    const uint4* x4 = (const uint4*)act;
    float xs[16];
    unpack8(x4[lane], xs);
    unpack8(x4[lane + 32], xs + 8);
#pragma unroll
    for (int n = 0; n < 7; n++) {
        const float4* w4 = (const float4*)((n < 6) ? (Wp + (size_t)n * U_) : Wv);
        float d = 0.f;
        float wf[8];
        *(float4*)(wf)     = w4[2 * lane];
        *(float4*)(wf + 4) = w4[2 * lane + 1];
#pragma unroll
        for (int t = 0; t < 8; t++) d += xs[t] * wf[t];
        *(float4*)(wf)     = w4[2 * (lane + 32)];
        *(float4*)(wf + 4) = w4[2 * (lane + 32) + 1];
#pragma unroll
        for (int t = 0; t < 8; t++) d += xs[8 + t] * wf[t];
#pragma unroll
        for (int off = 16; off > 0; off >>= 1) d += __shfl_xor_sync(~0u, d, off);
        if (lane == 0) {
            if (y == 0) {
                if (n < 6) agent_pol[(size_t)b * A_ + n] = d + bp[n];
                else       agent_val[b] = d + bv[0];
            } else {
                const int o = y - 1;
                if (n < 6) opp_pol[(size_t)b * (O_ * A_) + o * A_ + n] = d + bp[n];
                else       opp_val[(size_t)b * O_ + o] = d + bv[0];
            }
        }
    }
}

// ===========================================================================
extern "C" void kernel_launch(void* const* d_in, const int* in_sizes, int n_in,
                              void* d_out, int out_size)
{
    const float* features = (const float*)d_in[0];
    const float* W_al = (const float*)d_in[1];
    const float* b_al = (const float*)d_in[2];
    const float* W_in = (const float*)d_in[3];
    const float* b_in = (const float*)d_in[4];
    const float* W_out = (const float*)d_in[5];
    const float* b_out = (const float*)d_in[6];
    const float* W_ah = (const float*)d_in[7];
    const float* b_ah = (const float*)d_in[8];
    const float* W_ap = (const float*)d_in[9];
    const float* b_ap = (const float*)d_in[10];
    const float* W_av = (const float*)d_in[11];
    const float* b_av = (const float*)d_in[12];
    const float* W_ol = (const float*)d_in[13];
    const float* b_ol = (const float*)d_in[14];
    const float* W_oh = (const float*)d_in[15];
    const float* b_oh = (const float*)d_in[16];
    const float* W_op = (const float*)d_in[17];
    const float* b_op = (const float*)d_in[18];
    const float* W_ov = (const float*)d_in[19];
    const float* b_ov = (const float*)d_in[20];
    float* out = (float*)d_out;

    cudaFuncSetAttribute(gemm_k1,
                         cudaFuncAttributeMaxDynamicSharedMemorySize, GEMM_SMEM);
    cudaFuncSetAttribute(gemm_mid,
                         cudaFuncAttributeMaxDynamicSharedMemorySize, GEMM_SMEM);
    cudaFuncSetAttribute(gemm_fin,
                         cudaFuncAttributeMaxDynamicSharedMemorySize, GEMM_SMEM);

    const float qscale = 0.08838834764831845f;  // 1/sqrt(128)

    float* out_agent_policy = out;
    float* out_agent_value  = out + (size_t)B_ * A_;
    float* out_opp_policy   = out_agent_value + B_;
    float* out_opp_value    = out_opp_policy + (size_t)B_ * O_ * A_;
    float* out_infl         = out_opp_value + (size_t)B_ * O_;

    const dim3 gb(256);

    // 0) converts (+ W_out transpose, + W_ah-left copy)
    convert_all<<<(CTOT + 255) / 256, 256>>>(features, W_al, W_ol, W_in,
                                             W_out, W_ah, W_oh);
    // 0b) b_comb
    bcomb_kernel<<<64, 256>>>(W_ah, b_ah, b_out);
    // 1) agent_latent + opp_lat + W_comb
    gemm_k1<<<dim3(4, 64, 5), gb, GEMM_SMEM>>>(b_al, b_ol);
    // 2) q + kv + opp_heads + agent_head-partial (all K=512, uniform)
    gemm_mid<<<dim3(4, 64, 11), gb, GEMM_SMEM>>>(b_in, qscale, b_oh);
    // 3) attention (writes attn into cat[:, U:], + influences)
    attention_kernel<<<B_ / 2, 256>>>(out_infl);
    // 4) agent_head finish (attn half + partial, elu)
    gemm_fin<<<dim3(4, 64, 1), gb, GEMM_SMEM>>>();
    // 5) all skinny heads
    skinny_all<<<dim3(B_ / 8, 4), 256>>>(W_ap, b_ap, W_av, b_av,
                                         W_op, b_op, W_ov, b_ov,
                                         out_agent_policy, out_agent_value,
                                         out_opp_policy, out_opp_value);
}

// round 14
// speedup vs baseline: 1.0368x; 1.0368x over previous
#include <cuda_runtime.h>
#include <cuda_fp16.h>
#include <math.h>
#include <stdint.h>

// Problem constants
#define B_ 8192
#define F_ 1024
#define U_ 512
#define O_ 3
#define A_ 6
#define H_ 4
#define HD_ 128

typedef __half h16;
#define BU_ ((size_t)B_ * U_)
#define UF_ ((size_t)U_ * F_)

// ===========================================================================
// Scratch (device globals) — all activations fp16
// ===========================================================================
__device__ __align__(128) h16 g_feat[(size_t)B_ * F_];
__device__ __align__(128) h16 g_cat[(size_t)B_ * 2 * U_];     // [agent_latent | attn]
__device__ __align__(128) h16 g_opp[(size_t)O_ * B_ * U_];
__device__ __align__(128) h16 g_q[(size_t)B_ * U_];
__device__ __align__(128) h16 g_kv[(size_t)O_ * B_ * 2 * U_]; // [O][B][k|v]
__device__ __align__(128) h16 g_ah[(size_t)B_ * U_];
__device__ __align__(128) h16 g_oh[(size_t)O_ * B_ * U_];
// weights (fp16)
__device__ __align__(128) h16 g_Wbig[(size_t)4 * U_ * F_];    // [W_al | W_ol(3)]
__device__ __align__(128) h16 g_Win[(size_t)3 * U_ * U_];
__device__ __align__(128) h16 g_WoutT[(size_t)U_ * U_];       // W_out transposed
__device__ __align__(128) h16 g_Wah[(size_t)U_ * 2 * U_];     // full W_ah (comb A)
__device__ __align__(128) h16 g_Wah2[(size_t)U_ * 2 * U_];    // [W_ahL | W_comb]
__device__ __align__(128) h16 g_Woh[(size_t)O_ * U_ * U_];
__device__ __align__(128) float g_bcomb[U_];
__device__ __align__(128) float g_zero[U_];                   // stays zero

// ===========================================================================
// PTX helpers
// ===========================================================================
__device__ __forceinline__ uint32_t smem_u32(const void* p) {
    uint32_t a;
    asm("{ .reg .u64 t; cvta.to.shared.u64 t, %1; cvt.u32.u64 %0, t; }"
        : "=r"(a) : "l"(p));
    return a;
}
__device__ __forceinline__ void cp16(uint32_t s, const void* g) {
    asm volatile("cp.async.cg.shared.global [%0], [%1], 16;" :: "r"(s), "l"(g));
}
#define CP_COMMIT() asm volatile("cp.async.commit_group;" ::: "memory")
#define CP_WAIT0()  asm volatile("cp.async.wait_group 0;" ::: "memory")
#define CP_WAIT1()  asm volatile("cp.async.wait_group 1;" ::: "memory")

__device__ __forceinline__ void ldsm4(uint32_t* r, uint32_t addr) {
    asm volatile("ldmatrix.sync.aligned.m8n8.x4.shared.b16 {%0,%1,%2,%3}, [%4];"
                 : "=r"(r[0]), "=r"(r[1]), "=r"(r[2]), "=r"(r[3]) : "r"(addr));
}
__device__ __forceinline__ void mma_f16(float* c, const uint32_t* a, const uint32_t* b) {
    asm volatile("mma.sync.aligned.m16n8k16.row.col.f32.f16.f16.f32 "
                 "{%0,%1,%2,%3}, {%4,%5,%6,%7}, {%8,%9}, {%0,%1,%2,%3};"
                 : "+f"(c[0]), "+f"(c[1]), "+f"(c[2]), "+f"(c[3])
                 : "r"(a[0]), "r"(a[1]), "r"(a[2]), "r"(a[3]),
                   "r"(b[0]), "r"(b[1]));
}
__device__ __forceinline__ void unpack8(uint4 u, float* out) {
    const __half2* h = (const __half2*)&u;
#pragma unroll
    for (int j = 0; j < 4; j++) {
        float2 f = __half22float2(h[j]);
        out[2 * j] = f.x; out[2 * j + 1] = f.y;
    }
}
__device__ __forceinline__ float4 load_h4(const h16* p) {
    uint2 u = *(const uint2*)p;
    const __half2* h = (const __half2*)&u;
    float2 a = __half22float2(h[0]), b = __half22float2(h[1]);
    return make_float4(a.x, a.y, b.x, b.y);
}

// ===========================================================================
// One-shot convert + W_out transpose + W_ah-left copy + bcomb (trailing blocks)
// ===========================================================================
#define CN0 ((int)((size_t)B_ * F_ / 4))
#define CN1 ((int)(UF_ / 4))
#define CN2 ((int)(3 * UF_ / 4))
#define CN3 ((int)(3 * (size_t)U_ * U_ / 4))
#define CN4 ((int)((size_t)U_ * U_ / 4))
#define CN5 ((int)(2 * (size_t)U_ * U_ / 4))
#define CN6 ((int)((size_t)U_ * U_ / 4))
#define CN7 ((int)(3 * (size_t)U_ * U_ / 4))
#define CTOT (CN0 + CN1 + CN2 + CN3 + CN4 + CN5 + CN6 + CN7)
#define NBCONV ((CTOT + 255) / 256)
#define NBBC   64                               // 64 blocks x 8 warps = 512 outputs

__global__ void convert_all(const float* __restrict__ f,
                            const float* __restrict__ wal,
                            const float* __restrict__ wol,
                            const float* __restrict__ win,
                            const float* __restrict__ wout,
                            const float* __restrict__ wah,
                            const float* __restrict__ woh,
                            const float* __restrict__ b_ah,
                            const float* __restrict__ b_out)
{
    if (blockIdx.x >= NBCONV) {
        // bcomb: warp per output m
        const int w = (blockIdx.x - NBCONV) * 8 + (threadIdx.x >> 5);
        const int lane = threadIdx.x & 31;
        if (w >= U_) return;
        const float* row = wah + (size_t)w * 2 * U_ + U_;
        float s = 0.f;
#pragma unroll
        for (int j = 0; j < 16; j++) {
            const int n = lane + 32 * j;
            s += row[n] * b_out[n];
        }
#pragma unroll
        for (int off = 16; off > 0; off >>= 1) s += __shfl_xor_sync(~0u, s, off);
        if (lane == 0) g_bcomb[w] = s + b_ah[w];
        return;
    }

    int i = blockIdx.x * blockDim.x + threadIdx.x;
    if (i >= CTOT) return;
    const float* src; h16* dst; int off;
    if (i < CN0)                 { src = f;    dst = g_feat;       off = i; }
    else if ((i -= CN0) < CN1)   { src = wal;  dst = g_Wbig;       off = i; }
    else if ((i -= CN1) < CN2)   { src = wol;  dst = g_Wbig + UF_; off = i; }
    else if ((i -= CN2) < CN3)   { src = win;  dst = g_Win;        off = i; }
    else if ((i -= CN3) < CN4) {
        // W_out [U,U]: read float4 at row n, cols k..k+3; write transposed
        int n = i >> 7, k4 = i & 127;
        float4 x = ((const float4*)wout)[i];
        const float xs[4] = {x.x, x.y, x.z, x.w};
#pragma unroll
        for (int j = 0; j < 4; j++)
            g_WoutT[(size_t)(k4 * 4 + j) * U_ + n] = __float2half_rn(xs[j]);
        return;
    }
    else if ((i -= CN4) < CN5)   { src = wah;  dst = g_Wah;        off = i; }
    else if ((i -= CN5) < CN6) {
        // W_ah left half -> g_Wah2 left half
        int m = i >> 7, c4 = i & 127;
        int idx = m * 256 + c4;
        float4 x = ((const float4*)wah)[idx];
        h16 h[4] = {__float2half_rn(x.x), __float2half_rn(x.y),
                    __float2half_rn(x.z), __float2half_rn(x.w)};
        ((uint2*)g_Wah2)[idx] = *(uint2*)h;
        return;
    }
    else                         { src = woh;  dst = g_Woh;        off = i - CN6; }
    float4 x = ((const float4*)src)[off];
    h16 h[4] = {__float2half_rn(x.x), __float2half_rn(x.y),
                __float2half_rn(x.z), __float2half_rn(x.w)};
    ((uint2*)dst)[off] = *(uint2*)h;
}

// ===========================================================================
// GEMM core: C(h16) = act((A @ W^T + bias) * scale)
// CTA 128x128, 8 warps, K chunk 64, 3-stage cp.async ring, occ 2.
// ===========================================================================
#define MT 128
#define NT 128
#define KB 64
#define RSTRIDE 144
#define COMP_BYTES (128 * RSTRIDE)
#define OFF_A 0
#define OFF_W COMP_BYTES
#define STG_BYTES (2 * COMP_BYTES)
#define NSTAGE 3
#define GEMM_SMEM (1024 + NSTAGE * STG_BYTES)   // 111616

__device__ __forceinline__ void load_stage_async(
    uint32_t st, int tid,
    const h16* __restrict__ A, int lda, int mtile,
    const h16* __restrict__ W, int ldw, int ntile, int k0)
{
#pragma unroll
    for (int i = 0; i < 4; i++) {
        int idx = tid + i * 256;
        int r = idx >> 3, c = idx & 7;
        uint32_t so = (uint32_t)(r * RSTRIDE + c * 16);
        cp16(st + OFF_A + so, A + (size_t)(mtile + r) * lda + k0 + c * 8);
    }
#pragma unroll
    for (int i = 0; i < 4; i++) {
        int idx = tid + i * 256;
        int r = idx >> 3, c = idx & 7;
        uint32_t so = (uint32_t)(r * RSTRIDE + c * 16);
        cp16(st + OFF_W + so, W + (size_t)(ntile + r) * ldw + k0 + c * 8);
    }
    CP_COMMIT();
}

__device__ __forceinline__ void gemm_core(
    const h16* __restrict__ A, int lda,
    const h16* __restrict__ W, int ldw,
    const float* __restrict__ bias, float scale,
    h16* __restrict__ C, int ldc,
    int K, bool elu, char* smem)
{
    float* bias_s = (float*)smem;
    const uint32_t st0 = smem_u32(smem + 1024);

    const int tid = threadIdx.x, lane = tid & 31, wid = tid >> 5;
    const int wm = wid & 3, wn = wid >> 2;
    const int mtile = blockIdx.y * MT;
    const int ntile = blockIdx.x * NT;

    if (tid < NT) bias_s[tid] = bias[ntile + tid];

    float acc[2][8][4];
#pragma unroll
    for (int i = 0; i < 2; i++)
#pragma unroll
        for (int j = 0; j < 8; j++)
#pragma unroll
            for (int t = 0; t < 4; t++) acc[i][j][t] = 0.f;

    const int nc = K / KB;

    load_stage_async(st0, tid, A, lda, mtile, W, ldw, ntile, 0);
    load_stage_async(st0 + STG_BYTES, tid, A, lda, mtile, W, ldw, ntile, KB);

    const uint32_t a_row = (uint32_t)(lane & 15);
    const uint32_t a_koff = (uint32_t)((lane >> 4) * 16);
    const uint32_t b_row = (uint32_t)(((lane >> 4) * 8) + (lane & 7));
    const uint32_t b_koff = (uint32_t)(((lane >> 3) & 1) * 16);

    int sidx = 0;
    for (int c = 0; c < nc; ++c) {
        if (c + 1 < nc) CP_WAIT1(); else CP_WAIT0();
        __syncthreads();
        if (c + 2 < nc) {
            int nidx = sidx + 2; if (nidx >= NSTAGE) nidx -= NSTAGE;
            load_stage_async(st0 + nidx * STG_BYTES, tid,
                             A, lda, mtile, W, ldw, ntile, (c + 2) * KB);
        }
        const uint32_t cur = st0 + sidx * STG_BYTES;
#pragma unroll
        for (int kc = 0; kc < 4; kc++) {
            uint32_t af[2][4], wf[4][4];
#pragma unroll
            for (int mt = 0; mt < 2; mt++) {
                uint32_t row = wm * 32 + mt * 16 + a_row;
                ldsm4(af[mt], cur + OFF_A + row * RSTRIDE + kc * 32 + a_koff);
            }
#pragma unroll
            for (int q = 0; q < 4; q++) {
                uint32_t row = wn * 64 + q * 16 + b_row;
                ldsm4(wf[q], cur + OFF_W + row * RSTRIDE + kc * 32 + b_koff);
            }
#pragma unroll
            for (int mt = 0; mt < 2; mt++)
#pragma unroll
                for (int q = 0; q < 4; q++)
#pragma unroll
                    for (int s = 0; s < 2; s++)
                        mma_f16(acc[mt][2 * q + s], af[mt], &wf[q][2 * s]);
        }
        if (++sidx >= NSTAGE) sidx = 0;
    }

    const int g = lane >> 2, tg = lane & 3;
#pragma unroll
    for (int mt = 0; mt < 2; mt++) {
        const int m0 = mtile + wm * 32 + mt * 16 + g;
#pragma unroll
        for (int n8 = 0; n8 < 8; n8++) {
            const int nl = wn * 64 + n8 * 8 + tg * 2;
            const int n = ntile + nl;
            const float b0 = bias_s[nl], b1 = bias_s[nl + 1];
            float x0 = (acc[mt][n8][0] + b0) * scale;
            float x1 = (acc[mt][n8][1] + b1) * scale;
            float y0 = (acc[mt][n8][2] + b0) * scale;
            float y1 = (acc[mt][n8][3] + b1) * scale;
            if (elu) {
                x0 = x0 > 0.f ? x0 : expm1f(x0);
                x1 = x1 > 0.f ? x1 : expm1f(x1);
                y0 = y0 > 0.f ? y0 : expm1f(y0);
                y1 = y1 > 0.f ? y1 : expm1f(y1);
            }
            union { h16 h[2]; uint32_t u; } p;
            p.h[0] = __float2half_rn(x0); p.h[1] = __float2half_rn(x1);
            *(uint32_t*)(C + (size_t)m0 * ldc + n) = p.u;
            p.h[0] = __float2half_rn(y0); p.h[1] = __float2half_rn(y1);
            *(uint32_t*)(C + (size_t)(m0 + 8) * ldc + n) = p.u;
        }
    }
}

// ---- mode wrappers ----
// K1: z=0 agent_latent; z=1..3 opp_lat; z=4 (y<4) W_comb.  grid (4, 64, 5)
__global__ void __launch_bounds__(256, 2)
gemm_k1(const float* __restrict__ b_al, const float* __restrict__ b_ol)
{
    extern __shared__ __align__(128) char smem[];
    const int z = blockIdx.z;
    if (z == 0)
        gemm_core(g_feat, F_, g_Wbig, F_, b_al, 1.f,
                  g_cat, 2 * U_, F_, true, smem);
    else if (z < 4)
        gemm_core(g_feat, F_, g_Wbig + (size_t)z * UF_, F_,
                  b_ol + (size_t)(z - 1) * U_, 1.f,
                  g_opp + (size_t)(z - 1) * BU_, U_, F_, true, smem);
    else {
        if (blockIdx.y >= 4) return;
        gemm_core(g_Wah + U_, 2 * U_, g_WoutT, U_, g_zero, 1.f,
                  g_Wah2 + U_, 2 * U_, U_, false, smem);
    }
}

// QKV: zz=0 q (N=512); zz=1..6 kv halves. grid (4,64,7)
__global__ void __launch_bounds__(256, 2)
gemm_qkv(const float* __restrict__ b_in, float qscale)
{
    extern __shared__ __align__(128) char smem[];
    const int zz = blockIdx.z;
    if (zz == 0) {
        gemm_core(g_cat, 2 * U_, g_Win, U_, b_in, qscale,
                  g_q, U_, U_, false, smem);
    } else {
        const int o = (zz - 1) >> 1, half = (zz - 1) & 1;
        gemm_core(g_opp + (size_t)o * BU_, U_,
                  g_Win + (size_t)U_ * U_ + (size_t)half * 512 * U_, U_,
                  b_in + U_ + half * 512, 1.f,
                  g_kv + (size_t)o * B_ * 2 * U_ + half * 512, 2 * U_,
                  U_, false, smem);
    }
}

// HEADS: z=0 agent_head (K=2U, composed); z=1..3 opp_heads. grid (4,64,4)
__global__ void __launch_bounds__(256, 2)
gemm_heads(const float* __restrict__ b_oh)
{
    extern __shared__ __align__(128) char smem[];
    const int z = blockIdx.z;
    if (z == 0)
        gemm_core(g_cat, 2 * U_, g_Wah2, 2 * U_, g_bcomb, 1.f,
                  g_ah, U_, 2 * U_, true, smem);
    else
        gemm_core(g_opp + (size_t)(z - 1) * BU_, U_,
                  g_Woh + (size_t)(z - 1) * U_ * U_, U_,
                  b_oh + (size_t)(z - 1) * U_, 1.f,
                  g_oh + (size_t)(z - 1) * BU_, U_, U_, true, smem);
}

// ===========================================================================
// Attention — 2 rows per 256-thread CTA; writes attn into cat[:, U:]
// ===========================================================================
__global__ void attention_kernel(float* __restrict__ infl)
{
    const int tid = threadIdx.x;
    const int sub = tid >> 7;
    const int ltid = tid & 127;
    const int b = blockIdx.x * 2 + sub;
    const int h = ltid >> 5;
    const int lane = tid & 31;
    __shared__ float sw[2][H_][O_];

    const size_t qbase = (size_t)b * U_ + (size_t)h * HD_;
    const float4 qv = load_h4(g_q + qbase + lane * 4);

    float s[O_];
#pragma unroll
    for (int o = 0; o < O_; o++) {
        const size_t kb = ((size_t)o * B_ + b) * (2 * U_) + (size_t)h * HD_;
        const float4 kvv = load_h4(g_kv + kb + lane * 4);
        float d = qv.x * kvv.x + qv.y * kvv.y + qv.z * kvv.z + qv.w * kvv.w;
#pragma unroll
        for (int off = 16; off > 0; off >>= 1)
            d += __shfl_xor_sync(0xffffffffu, d, off);
        s[o] = d;
    }
    const float m = fmaxf(s[0], fmaxf(s[1], s[2]));
    const float e0 = expf(s[0] - m), e1 = expf(s[1] - m), e2 = expf(s[2] - m);
    const float inv = 1.f / (e0 + e1 + e2);
    const float w[O_] = {e0 * inv, e1 * inv, e2 * inv};

    float4 a = make_float4(0.f, 0.f, 0.f, 0.f);
#pragma unroll
    for (int o = 0; o < O_; o++) {
        const size_t vb = ((size_t)o * B_ + b) * (2 * U_) + U_ + (size_t)h * HD_;
        const float4 vv = load_h4(g_kv + vb + lane * 4);
        a.x = fmaf(w[o], vv.x, a.x);
        a.y = fmaf(w[o], vv.y, a.y);
        a.z = fmaf(w[o], vv.z, a.z);
        a.w = fmaf(w[o], vv.w, a.w);
    }
    {
        union { h16 h[4]; uint2 u; } uh;
        uh.h[0] = __float2half_rn(a.x); uh.h[1] = __float2half_rn(a.y);
        uh.h[2] = __float2half_rn(a.z); uh.h[3] = __float2half_rn(a.w);
        *(uint2*)(g_cat + (size_t)b * 2 * U_ + U_ + (size_t)h * HD_ + lane * 4) = uh.u;
    }

    if (lane == 0) {
        sw[sub][h][0] = w[0]; sw[sub][h][1] = w[1]; sw[sub][h][2] = w[2];
    }
    __syncthreads();
    if (ltid < O_)
        infl[(size_t)b * O_ + ltid] =
            0.25f * (sw[sub][0][ltid] + sw[sub][1][ltid] +
                     sw[sub][2][ltid] + sw[sub][3][ltid]);
}

// ===========================================================================
// Fused skinny heads — grid (B/8, 4): y=0 agent (g_ah), y>0 opp o=y-1 (g_oh)
// ===========================================================================
__global__ void skinny_all(const float* __restrict__ W_ap, const float* __restrict__ b_ap,
                           const float* __restrict__ W_av, const float* __restrict__ b_av,
                           const float* __restrict__ W_op, const float* __restrict__ b_op,
                           const float* __restrict__ W_ov, const float* __restrict__ b_ov,
                           float* __restrict__ agent_pol, float* __restrict__ agent_val,
                           float* __restrict__ opp_pol, float* __restrict__ opp_val)
{
    const int wid = threadIdx.x >> 5, lane = threadIdx.x & 31;
    const int b = blockIdx.x * 8 + wid;
    const int y = blockIdx.y;

    const h16* act; const float *Wp, *bp, *Wv, *bv;
    if (y == 0) {
        act = g_ah + (size_t)b * U_;
        Wp = W_ap; bp = b_ap; Wv = W_av; bv = b_av;
    } else {
        const int o = y - 1;
        act = g_oh + ((size_t)o * B_ + b) * U_;
        Wp = W_op + (size_t)o * A_ * U_; bp = b_op + o * A_;
        Wv = W_ov + (size_t)o * U_;      bv = b_ov + o;
    }

    const uint4* x4 = (const uint4*)act;
    float xs[16];
    unpack8(x4[lane], xs);
    unpack8(x4[lane + 32], xs + 8);
#pragma unroll
    for (int n = 0; n < 7; n++) {
        const float4* w4 = (const float4*)((n < 6) ? (Wp + (size_t)n * U_) : Wv);
        float d = 0.f;
        float wf[8];
        *(float4*)(wf)     = w4[2 * lane];
        *(float4*)(wf + 4) = w4[2 * lane + 1];
#pragma unroll
        for (int t = 0; t < 8; t++) d += xs[t] * wf[t];
        *(float4*)(wf)     = w4[2 * (lane + 32)];
        *(float4*)(wf + 4) = w4[2 * (lane + 32) + 1];
#pragma unroll
        for (int t = 0; t < 8; t++) d += xs[8 + t] * wf[t];
#pragma unroll
        for (int off = 16; off > 0; off >>= 1) d += __shfl_xor_sync(~0u, d, off);
        if (lane == 0) {
            if (y == 0) {
                if (n < 6) agent_pol[(size_t)b * A_ + n] = d + bp[n];
                else       agent_val[b] = d + bv[0];
            } else {
                const int o = y - 1;
                if (n < 6) opp_pol[(size_t)b * (O_ * A_) + o * A_ + n] = d + bp[n];
                else       opp_val[(size_t)b * O_ + o] = d + bv[0];
            }
        }
    }
}

// ===========================================================================
extern "C" void kernel_launch(void* const* d_in, const int* in_sizes, int n_in,
                              void* d_out, int out_size)
{
    const float* features = (const float*)d_in[0];
    const float* W_al = (const float*)d_in[1];
    const float* b_al = (const float*)d_in[2];
    const float* W_in = (const float*)d_in[3];
    const float* b_in = (const float*)d_in[4];
    const float* W_out = (const float*)d_in[5];
    const float* b_out = (const float*)d_in[6];
    const float* W_ah = (const float*)d_in[7];
    const float* b_ah = (const float*)d_in[8];
    const float* W_ap = (const float*)d_in[9];
    const float* b_ap = (const float*)d_in[10];
    const float* W_av = (const float*)d_in[11];
    const float* b_av = (const float*)d_in[12];
    const float* W_ol = (const float*)d_in[13];
    const float* b_ol = (const float*)d_in[14];
    const float* W_oh = (const float*)d_in[15];
    const float* b_oh = (const float*)d_in[16];
    const float* W_op = (const float*)d_in[17];
    const float* b_op = (const float*)d_in[18];
    const float* W_ov = (const float*)d_in[19];
    const float* b_ov = (const float*)d_in[20];
    float* out = (float*)d_out;

    cudaFuncSetAttribute(gemm_k1,
                         cudaFuncAttributeMaxDynamicSharedMemorySize, GEMM_SMEM);
    cudaFuncSetAttribute(gemm_qkv,
                         cudaFuncAttributeMaxDynamicSharedMemorySize, GEMM_SMEM);
    cudaFuncSetAttribute(gemm_heads,
                         cudaFuncAttributeMaxDynamicSharedMemorySize, GEMM_SMEM);

    const float qscale = 0.08838834764831845f;  // 1/sqrt(128)

    float* out_agent_policy = out;
    float* out_agent_value  = out + (size_t)B_ * A_;
    float* out_opp_policy   = out_agent_value + B_;
    float* out_opp_value    = out_opp_policy + (size_t)B_ * O_ * A_;
    float* out_infl         = out_opp_value + (size_t)B_ * O_;

    const dim3 gb(256);

    // 0) converts (+ W_out transpose, + W_ah-left copy, + bcomb tail blocks)
    convert_all<<<NBCONV + NBBC, 256>>>(features, W_al, W_ol, W_in,
                                        W_out, W_ah, W_oh, b_ah, b_out);
    // 1) agent_latent + opp_lat + W_comb (z=5; z=4 only y<4 active)
    gemm_k1<<<dim3(4, 64, 5), gb, GEMM_SMEM>>>(b_al, b_ol);
    // 2) q + kv (zz=7)
    gemm_qkv<<<dim3(4, 64, 7), gb, GEMM_SMEM>>>(b_in, qscale);
    // 3) attention (writes attn into cat[:, U:], + influences)
    attention_kernel<<<B_ / 2, 256>>>(out_infl);
    // 4) agent_head (composed) + opp_heads (z=4)
    gemm_heads<<<dim3(4, 64, 4), gb, GEMM_SMEM>>>(b_oh);
    // 5) all skinny heads
    skinny_all<<<dim3(B_ / 8, 4), 256>>>(W_ap, b_ap, W_av, b_av,
                                         W_op, b_op, W_ov, b_ov,
                                         out_agent_policy, out_agent_value,
                                         out_opp_policy, out_opp_value);
}